// round 14
// baseline (speedup 1.0000x reference)
#include <cuda_runtime.h>
#include <cuda_fp16.h>
#include <math.h>

#define NN 100000
#define EE 1600000
#define ET 1700000          // EE + NN self loops
#define EDIM 8
#define HH 4
#define NEG 0.2f
#define EPSV 1e-16f
#define SCAN_BLK 1024
#define NBLK ((NN + SCAN_BLK - 1) / SCAN_BLK)   // 98
#define FULLM 0xffffffffu

// ---------------- static device scratch ----------------
__device__ int      g_src[ET];
__device__ int      g_dst[ET];
__device__ int      g_deg[NN];
__device__ int      g_row[NN + 1];
__device__ int      g_woff[NN];
__device__ int      g_bsum[NBLK];
__device__ int      g_bscan[NBLK];
__device__ int      g_csrc[ET];                 // CSR: src per slot
__device__ __align__(16) float  g_ae1[ET * HH]; // CSR-ordered edge attention, layer 1
__device__ __align__(16) float  g_ae2[ET * HH]; // CSR-ordered edge attention, layer 2
__device__ __align__(16) __half g_h16[NN * 128];// per-node head features, fp16 payload
__device__ __align__(16) float  g_x2[NN * 32];  // layer-2 input (fp32)
__device__ __align__(16) float  g_as[NN * HH];
__device__ __align__(16) float  g_ad[NN * HH];
__device__ float    g_ve1[HH * EDIM];
__device__ float    g_ve2[HH * EDIM];
__device__ unsigned g_odd_or = 0u;   // static zero; atomicOr is idempotent across replays

// ---------------- dtype detection (int32 vs int64) + deg zero ----------------
__global__ void detect_kernel(const unsigned* __restrict__ w) {
    int i = blockIdx.x * blockDim.x + threadIdx.x;
    if (i < NN) g_deg[i] = 0;
    unsigned acc = 0u;
    if (i < EE) acc = w[2 * (size_t)i + 1];
    #pragma unroll
    for (int off = 16; off > 0; off >>= 1)
        acc |= __shfl_xor_sync(FULLM, acc, off);
    if ((threadIdx.x & 31) == 0 && acc) atomicOr(&g_odd_or, acc);
}

// decode edges (+ self loops), clamp, histogram of dst
__global__ void prep_edges_kernel(const void* __restrict__ eiv) {
    int e = blockIdx.x * blockDim.x + threadIdx.x;
    if (e >= ET) return;
    int s, d;
    if (e < EE) {
        if (g_odd_or != 0u) {                  // int32 layout
            const int* p = (const int*)eiv;
            s = p[e];
            d = p[(size_t)EE + e];
        } else {                               // int64 layout
            const long long* p = (const long long*)eiv;
            s = (int)p[e];
            d = (int)p[(size_t)EE + e];
        }
        s = s < 0 ? 0 : (s >= NN ? NN - 1 : s);
        d = d < 0 ? 0 : (d >= NN ? NN - 1 : d);
    } else {
        s = d = e - EE;
    }
    g_src[e] = s;
    g_dst[e] = d;
    atomicAdd(&g_deg[d], 1);
}

// ---------------- exclusive scan of g_deg -> g_row ----------------
__global__ void scan_a_kernel() {
    __shared__ int part[256];
    int b = blockIdx.x, t = threadIdx.x;
    int base = b * SCAN_BLK + t * 4;
    int v[4];
    #pragma unroll
    for (int j = 0; j < 4; j++) v[j] = (base + j < NN) ? g_deg[base + j] : 0;
    int tsum = v[0] + v[1] + v[2] + v[3];
    part[t] = tsum;
    __syncthreads();
    for (int off = 1; off < 256; off <<= 1) {
        int x = (t >= off) ? part[t - off] : 0;
        __syncthreads();
        part[t] += x;
        __syncthreads();
    }
    if (t == 255) g_bsum[b] = part[255];
    int run = part[t] - tsum;
    #pragma unroll
    for (int j = 0; j < 4; j++) {
        if (base + j < NN) g_row[base + j] = run;
        run += v[j];
    }
}

// scan_b + ve fold (independent work packed into one launch)
__global__ void scan_b_kernel(const float* __restrict__ We1, const float* __restrict__ ae1v,
                              const float* __restrict__ We2, const float* __restrict__ ae2v) {
    __shared__ int sb[128];
    int t = threadIdx.x;
    int v = (t < NBLK) ? g_bsum[t] : 0;
    sb[t] = v;
    __syncthreads();
    for (int off = 1; off < 128; off <<= 1) {
        int x = (t >= off) ? sb[t - off] : 0;
        __syncthreads();
        sb[t] += x;
        __syncthreads();
    }
    if (t < NBLK) g_bscan[t] = sb[t] - v;
    // ve[h*8+d] = sum_c We[d, h*C+c] * a_edge[h, c], both layers
    if (t < 32) {
        int h = t / EDIM, d = t % EDIM;
        float s = 0.f;
        #pragma unroll
        for (int c = 0; c < 32; c++) s += We1[d * 128 + h * 32 + c] * ae1v[h * 32 + c];
        g_ve1[t] = s;
    } else if (t < 64) {
        int u = t - 32;
        int h = u / EDIM, d = u % EDIM;
        float s = 0.f;
        #pragma unroll
        for (int c = 0; c < 16; c++) s += We2[d * 64 + h * 16 + c] * ae2v[h * 16 + c];
        g_ve2[u] = s;
    }
}

__global__ void scan_c_kernel() {
    int i = blockIdx.x * blockDim.x + threadIdx.x;
    if (i < NN) {
        int r = g_row[i] + g_bscan[i / SCAN_BLK];
        g_row[i] = r;
        g_woff[i] = r;
    }
    if (i == 0) g_row[NN] = ET;
}

// scatter edges to CSR slots; fold edge-attr attention dots for BOTH layers
__global__ void scatter_kernel(const float* __restrict__ edge_attr) {
    __shared__ float v1[HH * EDIM], v2[HH * EDIM];
    if (threadIdx.x < HH * EDIM) v1[threadIdx.x] = g_ve1[threadIdx.x];
    else if (threadIdx.x < 2 * HH * EDIM) v2[threadIdx.x - HH * EDIM] = g_ve2[threadIdx.x - HH * EDIM];
    __syncthreads();
    int e = blockIdx.x * blockDim.x + threadIdx.x;
    if (e >= ET) return;
    int d = g_dst[e];
    int p = atomicAdd(&g_woff[d], 1);
    g_csrc[p] = g_src[e];
    float4 a1 = make_float4(0.f, 0.f, 0.f, 0.f);
    float4 a2 = make_float4(0.f, 0.f, 0.f, 0.f);
    if (e < EE) {
        float4 ea0 = __ldg((const float4*)(edge_attr + (size_t)e * EDIM));
        float4 ea1 = __ldg((const float4*)(edge_attr + (size_t)e * EDIM + 4));
        float eav[8] = {ea0.x, ea0.y, ea0.z, ea0.w, ea1.x, ea1.y, ea1.z, ea1.w};
        float r1[HH], r2[HH];
        #pragma unroll
        for (int h = 0; h < HH; h++) {
            float s1 = 0.f, s2 = 0.f;
            #pragma unroll
            for (int k = 0; k < EDIM; k++) {
                s1 += eav[k] * v1[h * EDIM + k];
                s2 += eav[k] * v2[h * EDIM + k];
            }
            r1[h] = s1; r2[h] = s2;
        }
        a1 = make_float4(r1[0], r1[1], r1[2], r1[3]);
        a2 = make_float4(r2[0], r2[1], r2[2], r2[3]);
    }
    ((float4*)g_ae1)[p] = a1;
    ((float4*)g_ae2)[p] = a2;
}

__device__ __forceinline__ uint2 pack_half4(float4 a) {
    __half2 h01 = __float22half2_rn(make_float2(a.x, a.y));
    __half2 h23 = __float22half2_rn(make_float2(a.z, a.w));
    uint2 u;
    u.x = *reinterpret_cast<unsigned*>(&h01);
    u.y = *reinterpret_cast<unsigned*>(&h23);
    return u;
}

// ---------------- register-tiled GEMMs (4x4 per thread) + attention dots ----------------
// layer 1: Fin=64, HC=128, C=32. 256 threads, 32 rows/block. fp16 h store, fp32 att dots.
__global__ void gemm1_kernel(const float* __restrict__ x,
                             const float* __restrict__ W,
                             const float* __restrict__ a_src,
                             const float* __restrict__ a_dst) {
    __shared__ float Ws[64 * 128];
    __shared__ float xsT[64 * 36];     // transposed, pad 36 (16B-aligned rows)
    __shared__ float asv[128], adv[128];
    int t = threadIdx.x;
    for (int i = t; i < 64 * 128; i += 256) Ws[i] = W[i];
    if (t < 128) { asv[t] = a_src[t]; adv[t] = a_dst[t]; }
    int n0 = blockIdx.x * 32;
    for (int i = t; i < 2048; i += 256) {
        int r = i >> 6, f = i & 63;
        xsT[f * 36 + r] = x[(size_t)(n0 + r) * 64 + f];
    }
    __syncthreads();

    int tx = t & 31, ty = t >> 5;
    int c0 = tx * 4;
    float4 acc0 = {0,0,0,0}, acc1 = {0,0,0,0}, acc2 = {0,0,0,0}, acc3 = {0,0,0,0};
    #pragma unroll
    for (int f = 0; f < 64; f++) {
        float4 wv = *(const float4*)&Ws[f * 128 + c0];
        float4 xv = *(const float4*)&xsT[f * 36 + ty * 4];
        acc0.x += xv.x * wv.x; acc0.y += xv.x * wv.y; acc0.z += xv.x * wv.z; acc0.w += xv.x * wv.w;
        acc1.x += xv.y * wv.x; acc1.y += xv.y * wv.y; acc1.z += xv.y * wv.z; acc1.w += xv.y * wv.w;
        acc2.x += xv.z * wv.x; acc2.y += xv.z * wv.y; acc2.z += xv.z * wv.z; acc2.w += xv.z * wv.w;
        acc3.x += xv.w * wv.x; acc3.y += xv.w * wv.y; acc3.z += xv.w * wv.z; acc3.w += xv.w * wv.w;
    }
    int head = tx >> 3;
    float4 av = *(const float4*)&asv[c0];
    float4 dv = *(const float4*)&adv[c0];
    #pragma unroll
    for (int j = 0; j < 4; j++) {
        float4 a = (j == 0) ? acc0 : (j == 1) ? acc1 : (j == 2) ? acc2 : acc3;
        int n = n0 + ty * 4 + j;
        ((uint2*)g_h16)[(size_t)n * 32 + tx] = pack_half4(a);
        float ps = a.x * av.x + a.y * av.y + a.z * av.z + a.w * av.w;
        float pd = a.x * dv.x + a.y * dv.y + a.z * dv.z + a.w * dv.w;
        #pragma unroll
        for (int off = 1; off <= 4; off <<= 1) {
            ps += __shfl_xor_sync(FULLM, ps, off);
            pd += __shfl_xor_sync(FULLM, pd, off);
        }
        if ((tx & 7) == 0) {
            g_as[n * HH + head] = ps;
            g_ad[n * HH + head] = pd;
        }
    }
}

// layer 2: Fin=32, HC=64, C=16. 128 threads, 32 rows/block.
__global__ void gemm2_kernel(const float* __restrict__ x,
                             const float* __restrict__ W,
                             const float* __restrict__ a_src,
                             const float* __restrict__ a_dst) {
    __shared__ float Ws[32 * 64];
    __shared__ float xsT[32 * 36];
    __shared__ float asv[64], adv[64];
    int t = threadIdx.x;
    for (int i = t; i < 32 * 64; i += 128) Ws[i] = W[i];
    if (t < 64) { asv[t] = a_src[t]; adv[t] = a_dst[t]; }
    int n0 = blockIdx.x * 32;
    for (int i = t; i < 1024; i += 128) {
        int r = i >> 5, f = i & 31;
        xsT[f * 36 + r] = x[(size_t)(n0 + r) * 32 + f];
    }
    __syncthreads();

    int tx = t & 15, ty = t >> 4;
    int c0 = tx * 4;
    float4 acc0 = {0,0,0,0}, acc1 = {0,0,0,0}, acc2 = {0,0,0,0}, acc3 = {0,0,0,0};
    #pragma unroll
    for (int f = 0; f < 32; f++) {
        float4 wv = *(const float4*)&Ws[f * 64 + c0];
        float4 xv = *(const float4*)&xsT[f * 36 + ty * 4];
        acc0.x += xv.x * wv.x; acc0.y += xv.x * wv.y; acc0.z += xv.x * wv.z; acc0.w += xv.x * wv.w;
        acc1.x += xv.y * wv.x; acc1.y += xv.y * wv.y; acc1.z += xv.y * wv.z; acc1.w += xv.y * wv.w;
        acc2.x += xv.z * wv.x; acc2.y += xv.z * wv.y; acc2.z += xv.z * wv.z; acc2.w += xv.z * wv.w;
        acc3.x += xv.w * wv.x; acc3.y += xv.w * wv.y; acc3.z += xv.w * wv.z; acc3.w += xv.w * wv.w;
    }
    int head = tx >> 2;
    float4 av = *(const float4*)&asv[c0];
    float4 dv = *(const float4*)&adv[c0];
    #pragma unroll
    for (int j = 0; j < 4; j++) {
        float4 a = (j == 0) ? acc0 : (j == 1) ? acc1 : (j == 2) ? acc2 : acc3;
        int n = n0 + ty * 4 + j;
        ((uint2*)g_h16)[(size_t)n * 16 + tx] = pack_half4(a);
        float ps = a.x * av.x + a.y * av.y + a.z * av.z + a.w * av.w;
        float pd = a.x * dv.x + a.y * dv.y + a.z * dv.z + a.w * dv.w;
        #pragma unroll
        for (int off = 1; off <= 2; off <<= 1) {
            ps += __shfl_xor_sync(FULLM, ps, off);
            pd += __shfl_xor_sync(FULLM, pd, off);
        }
        if ((tx & 3) == 0) {
            g_as[n * HH + head] = ps;
            g_ad[n * HH + head] = pd;
        }
    }
}

__device__ __forceinline__ float selh(float4 v, int h) {
    return h == 0 ? v.x : (h == 1 ? v.y : (h == 2 ? v.z : v.w));
}

__device__ __forceinline__ void fma_half8(float* acc, float w, uint4 u) {
    float2 f0 = __half22float2(*reinterpret_cast<__half2*>(&u.x));
    float2 f1 = __half22float2(*reinterpret_cast<__half2*>(&u.y));
    float2 f2 = __half22float2(*reinterpret_cast<__half2*>(&u.z));
    float2 f3 = __half22float2(*reinterpret_cast<__half2*>(&u.w));
    acc[0] += w * f0.x; acc[1] += w * f0.y; acc[2] += w * f1.x; acc[3] += w * f1.y;
    acc[4] += w * f2.x; acc[5] += w * f2.y; acc[6] += w * f3.x; acc[7] += w * f3.y;
}

// fused layer (HC=128): phase-1 lane-per-edge exp; phase-2 half-warp per edge,
// uint4 (8-half) gathers, 4 edges per iteration, registers accumulate unnormalized.
__global__ void fused_layer128_kernel(const float* __restrict__ b,
                                      float* __restrict__ out,
                                      const float* __restrict__ ae_csr) {
    int n = (blockIdx.x * blockDim.x + threadIdx.x) >> 5;
    int lane = threadIdx.x & 31;
    if (n >= NN) return;
    int rs = g_row[n], re = g_row[n + 1];
    float4 ad4 = *(const float4*)&g_ad[n * HH];
    const float4* aecsr4 = (const float4*)ae_csr;
    const uint4* h4 = (const uint4*)g_h16;       // 16 uint4 per node row
    int half = lane >> 4;
    int l = lane & 15;
    int head = l >> 2;                           // 8 halves per lane, 32 per head

    float acc[8] = {0,0,0,0,0,0,0,0};
    float4 ds = make_float4(0.f, 0.f, 0.f, 0.f);

    for (int i0 = rs; i0 < re; i0 += 32) {
        int i = i0 + lane;
        int s = 0;
        float e0 = 0.f, e1 = 0.f, e2 = 0.f, e3 = 0.f;
        if (i < re) {
            s = g_csrc[i];
            float4 as4 = *(const float4*)&g_as[s * HH];
            float4 ae4 = aecsr4[i];
            float a0 = as4.x + ad4.x + ae4.x; a0 = a0 > 0.f ? a0 : NEG * a0;
            float a1 = as4.y + ad4.y + ae4.y; a1 = a1 > 0.f ? a1 : NEG * a1;
            float a2 = as4.z + ad4.z + ae4.z; a2 = a2 > 0.f ? a2 : NEG * a2;
            float a3 = as4.w + ad4.w + ae4.w; a3 = a3 > 0.f ? a3 : NEG * a3;
            e0 = __expf(a0); e1 = __expf(a1); e2 = __expf(a2); e3 = __expf(a3);
        }
        ds.x += e0; ds.y += e1; ds.z += e2; ds.w += e3;
        int cnt = min(32, re - i0);
        for (int j0 = 0; j0 < cnt; j0 += 4) {
            int jA = j0 + half * 2;              // half 0: j0,j0+1; half 1: j0+2,j0+3
            int jB = jA + 1;
            int jcA = jA < cnt ? jA : cnt - 1;
            int jcB = jB < cnt ? jB : cnt - 1;
            int sA = __shfl_sync(FULLM, s, jcA);
            int sB = __shfl_sync(FULLM, s, jcB);
            float wA0 = __shfl_sync(FULLM, e0, jcA), wA1 = __shfl_sync(FULLM, e1, jcA);
            float wA2 = __shfl_sync(FULLM, e2, jcA), wA3 = __shfl_sync(FULLM, e3, jcA);
            float wB0 = __shfl_sync(FULLM, e0, jcB), wB1 = __shfl_sync(FULLM, e1, jcB);
            float wB2 = __shfl_sync(FULLM, e2, jcB), wB3 = __shfl_sync(FULLM, e3, jcB);
            float wA = head == 0 ? wA0 : head == 1 ? wA1 : head == 2 ? wA2 : wA3;
            float wB = head == 0 ? wB0 : head == 1 ? wB1 : head == 2 ? wB2 : wB3;
            uint4 hA = h4[(size_t)sA * 16 + l];
            uint4 hB = h4[(size_t)sB * 16 + l];
            if (jA < cnt) fma_half8(acc, wA, hA);
            if (jB < cnt) fma_half8(acc, wB, hB);
        }
    }
    #pragma unroll
    for (int off = 16; off > 0; off >>= 1) {
        ds.x += __shfl_xor_sync(FULLM, ds.x, off);
        ds.y += __shfl_xor_sync(FULLM, ds.y, off);
        ds.z += __shfl_xor_sync(FULLM, ds.z, off);
        ds.w += __shfl_xor_sync(FULLM, ds.w, off);
    }
    float rdh = 1.f / (selh(ds, head) + EPSV);
    #pragma unroll
    for (int k = 0; k < 8; k++) acc[k] *= rdh;
    // combine halves (xor 16), then head mean (xor 4, xor 8)
    #pragma unroll
    for (int k = 0; k < 8; k++) {
        acc[k] += __shfl_xor_sync(FULLM, acc[k], 16);
        acc[k] += __shfl_xor_sync(FULLM, acc[k], 4);
        acc[k] += __shfl_xor_sync(FULLM, acc[k], 8);
    }
    if (lane < 4) {                               // lane λ holds channels [8λ, 8λ+8)
        float4 bA = ((const float4*)b)[lane * 2];
        float4 bB = ((const float4*)b)[lane * 2 + 1];
        float4 vA, vB;
        vA.x = 0.25f * acc[0] + bA.x; vA.x = vA.x > 0.f ? vA.x : expm1f(vA.x);
        vA.y = 0.25f * acc[1] + bA.y; vA.y = vA.y > 0.f ? vA.y : expm1f(vA.y);
        vA.z = 0.25f * acc[2] + bA.z; vA.z = vA.z > 0.f ? vA.z : expm1f(vA.z);
        vA.w = 0.25f * acc[3] + bA.w; vA.w = vA.w > 0.f ? vA.w : expm1f(vA.w);
        vB.x = 0.25f * acc[4] + bB.x; vB.x = vB.x > 0.f ? vB.x : expm1f(vB.x);
        vB.y = 0.25f * acc[5] + bB.y; vB.y = vB.y > 0.f ? vB.y : expm1f(vB.y);
        vB.z = 0.25f * acc[6] + bB.z; vB.z = vB.z > 0.f ? vB.z : expm1f(vB.z);
        vB.w = 0.25f * acc[7] + bB.w; vB.w = vB.w > 0.f ? vB.w : expm1f(vB.w);
        ((float4*)out)[(size_t)n * 8 + lane * 2]     = vA;
        ((float4*)out)[(size_t)n * 8 + lane * 2 + 1] = vB;
    }
}

// fused layer (HC=64): quarter-warp per edge, uint4 gathers, 8 edges per iteration.
__global__ void fused_layer64_kernel(const float* __restrict__ b,
                                     float* __restrict__ out,
                                     const float* __restrict__ ae_csr) {
    int n = (blockIdx.x * blockDim.x + threadIdx.x) >> 5;
    int lane = threadIdx.x & 31;
    if (n >= NN) return;
    int rs = g_row[n], re = g_row[n + 1];
    float4 ad4 = *(const float4*)&g_ad[n * HH];
    const float4* aecsr4 = (const float4*)ae_csr;
    const uint4* h4 = (const uint4*)g_h16;       // 8 uint4 per node row
    int quarter = lane >> 3;
    int l = lane & 7;
    int head = l >> 1;                           // 8 halves per lane, 16 per head

    float acc[8] = {0,0,0,0,0,0,0,0};
    float4 ds = make_float4(0.f, 0.f, 0.f, 0.f);

    for (int i0 = rs; i0 < re; i0 += 32) {
        int i = i0 + lane;
        int s = 0;
        float e0 = 0.f, e1 = 0.f, e2 = 0.f, e3 = 0.f;
        if (i < re) {
            s = g_csrc[i];
            float4 as4 = *(const float4*)&g_as[s * HH];
            float4 ae4 = aecsr4[i];
            float a0 = as4.x + ad4.x + ae4.x; a0 = a0 > 0.f ? a0 : NEG * a0;
            float a1 = as4.y + ad4.y + ae4.y; a1 = a1 > 0.f ? a1 : NEG * a1;
            float a2 = as4.z + ad4.z + ae4.z; a2 = a2 > 0.f ? a2 : NEG * a2;
            float a3 = as4.w + ad4.w + ae4.w; a3 = a3 > 0.f ? a3 : NEG * a3;
            e0 = __expf(a0); e1 = __expf(a1); e2 = __expf(a2); e3 = __expf(a3);
        }
        ds.x += e0; ds.y += e1; ds.z += e2; ds.w += e3;
        int cnt = min(32, re - i0);
        for (int j0 = 0; j0 < cnt; j0 += 8) {
            int jA = j0 + quarter * 2;           // quarter q: j0+2q, j0+2q+1
            int jB = jA + 1;
            int jcA = jA < cnt ? jA : cnt - 1;
            int jcB = jB < cnt ? jB : cnt - 1;
            int sA = __shfl_sync(FULLM, s, jcA);
            int sB = __shfl_sync(FULLM, s, jcB);
            float wA0 = __shfl_sync(FULLM, e0, jcA), wA1 = __shfl_sync(FULLM, e1, jcA);
            float wA2 = __shfl_sync(FULLM, e2, jcA), wA3 = __shfl_sync(FULLM, e3, jcA);
            float wB0 = __shfl_sync(FULLM, e0, jcB), wB1 = __shfl_sync(FULLM, e1, jcB);
            float wB2 = __shfl_sync(FULLM, e2, jcB), wB3 = __shfl_sync(FULLM, e3, jcB);
            float wA = head == 0 ? wA0 : head == 1 ? wA1 : head == 2 ? wA2 : wA3;
            float wB = head == 0 ? wB0 : head == 1 ? wB1 : head == 2 ? wB2 : wB3;
            uint4 hA = h4[(size_t)sA * 8 + l];
            uint4 hB = h4[(size_t)sB * 8 + l];
            if (jA < cnt) fma_half8(acc, wA, hA);
            if (jB < cnt) fma_half8(acc, wB, hB);
        }
    }
    #pragma unroll
    for (int off = 16; off > 0; off >>= 1) {
        ds.x += __shfl_xor_sync(FULLM, ds.x, off);
        ds.y += __shfl_xor_sync(FULLM, ds.y, off);
        ds.z += __shfl_xor_sync(FULLM, ds.z, off);
        ds.w += __shfl_xor_sync(FULLM, ds.w, off);
    }
    float rdh = 1.f / (selh(ds, head) + EPSV);
    #pragma unroll
    for (int k = 0; k < 8; k++) acc[k] *= rdh;
    // combine quarters (xor 8, 16), then head mean (xor 2, 4)
    #pragma unroll
    for (int k = 0; k < 8; k++) {
        acc[k] += __shfl_xor_sync(FULLM, acc[k], 8);
        acc[k] += __shfl_xor_sync(FULLM, acc[k], 16);
        acc[k] += __shfl_xor_sync(FULLM, acc[k], 2);
        acc[k] += __shfl_xor_sync(FULLM, acc[k], 4);
    }
    if (lane < 2) {                               // lane λ holds channels [8λ, 8λ+8)
        float4 bA = ((const float4*)b)[lane * 2];
        float4 bB = ((const float4*)b)[lane * 2 + 1];
        float4 vA, vB;
        vA.x = 0.25f * acc[0] + bA.x; vA.x = vA.x > 0.f ? vA.x : expm1f(vA.x);
        vA.y = 0.25f * acc[1] + bA.y; vA.y = vA.y > 0.f ? vA.y : expm1f(vA.y);
        vA.z = 0.25f * acc[2] + bA.z; vA.z = vA.z > 0.f ? vA.z : expm1f(vA.z);
        vA.w = 0.25f * acc[3] + bA.w; vA.w = vA.w > 0.f ? vA.w : expm1f(vA.w);
        vB.x = 0.25f * acc[4] + bB.x; vB.x = vB.x > 0.f ? vB.x : expm1f(vB.x);
        vB.y = 0.25f * acc[5] + bB.y; vB.y = vB.y > 0.f ? vB.y : expm1f(vB.y);
        vB.z = 0.25f * acc[6] + bB.z; vB.z = vB.z > 0.f ? vB.z : expm1f(vB.z);
        vB.w = 0.25f * acc[7] + bB.w; vB.w = vB.w > 0.f ? vB.w : expm1f(vB.w);
        ((float4*)out)[(size_t)n * 4 + lane * 2]     = vA;
        ((float4*)out)[(size_t)n * 4 + lane * 2 + 1] = vB;
    }
}

// ---------------- launch ----------------
extern "C" void kernel_launch(void* const* d_in, const int* in_sizes, int n_in,
                              void* d_out, int out_size) {
    const float* x   = (const float*)d_in[0];
    const void*  ei  = d_in[1];
    const float* ea  = (const float*)d_in[2];
    const float* W1  = (const float*)d_in[3];
    const float* We1 = (const float*)d_in[4];
    const float* as1 = (const float*)d_in[5];
    const float* ad1 = (const float*)d_in[6];
    const float* ae1 = (const float*)d_in[7];
    const float* b1  = (const float*)d_in[8];
    const float* W2  = (const float*)d_in[9];
    const float* We2 = (const float*)d_in[10];
    const float* as2 = (const float*)d_in[11];
    const float* ad2 = (const float*)d_in[12];
    const float* ae2 = (const float*)d_in[13];
    const float* b2  = (const float*)d_in[14];
    float* out = (float*)d_out;

    float* x2p = nullptr;
    float* ae1p = nullptr;
    float* ae2p = nullptr;
    cudaGetSymbolAddress((void**)&x2p, g_x2);
    cudaGetSymbolAddress((void**)&ae1p, g_ae1);
    cudaGetSymbolAddress((void**)&ae2p, g_ae2);

    const int TB = 256;

    // graph preprocessing (once per call) — 6 launches
    detect_kernel<<<(EE + TB - 1) / TB, TB>>>((const unsigned*)ei);
    prep_edges_kernel<<<(ET + TB - 1) / TB, TB>>>(ei);
    scan_a_kernel<<<NBLK, 256>>>();
    scan_b_kernel<<<1, 128>>>(We1, ae1, We2, ae2);
    scan_c_kernel<<<(NN + TB - 1) / TB, TB>>>();
    scatter_kernel<<<(ET + TB - 1) / TB, TB>>>(ea);

    // ---- layer 1: Fin=64, HC=128, C=32 ----
    gemm1_kernel<<<NN / 32, 256>>>(x, W1, as1, ad1);
    fused_layer128_kernel<<<(NN * 32 + TB - 1) / TB, TB>>>(b1, x2p, ae1p);

    // ---- layer 2: Fin=32, HC=64, C=16 ----
    gemm2_kernel<<<NN / 32, 128>>>(x2p, W2, as2, ad2);
    fused_layer64_kernel<<<(NN * 32 + TB - 1) / TB, TB>>>(b2, out, ae2p);
}

// round 15
// speedup vs baseline: 1.0264x; 1.0264x over previous
#include <cuda_runtime.h>
#include <cuda_fp16.h>
#include <math.h>

#define NN 100000
#define EE 1600000
#define ET 1700000          // EE + NN self loops
#define EDIM 8
#define HH 4
#define NEG 0.2f
#define EPSV 1e-16f
#define SCAN_BLK 1024
#define NBLK ((NN + SCAN_BLK - 1) / SCAN_BLK)   // 98
#define FULLM 0xffffffffu

// ---------------- static device scratch ----------------
__device__ int      g_src[ET];
__device__ int      g_dst[ET];
__device__ int      g_deg[NN];
__device__ int      g_row[NN + 1];
__device__ int      g_woff[NN];
__device__ int      g_bsum[NBLK];
__device__ int      g_bscan[NBLK];
__device__ int      g_csrc[ET];                 // CSR: src per slot
__device__ __align__(16) float  g_ae1[ET * HH]; // CSR-ordered edge attention, layer 1
__device__ __align__(16) float  g_ae2[ET * HH]; // CSR-ordered edge attention, layer 2
__device__ __align__(16) __half g_h16[NN * 128];// per-node head features, fp16 payload
__device__ __align__(16) float  g_x2[NN * 32];  // layer-2 input (fp32)
__device__ __align__(16) float  g_as[NN * HH];
__device__ __align__(16) float  g_ad[NN * HH];
__device__ float    g_ve1[HH * EDIM];
__device__ float    g_ve2[HH * EDIM];
__device__ unsigned g_odd_or = 0u;   // static zero; atomicOr is idempotent across replays

// ---------------- dtype detection (int32 vs int64) + deg zero ----------------
__global__ void detect_kernel(const unsigned* __restrict__ w) {
    int i = blockIdx.x * blockDim.x + threadIdx.x;
    if (i < NN) g_deg[i] = 0;
    unsigned acc = 0u;
    if (i < EE) acc = w[2 * (size_t)i + 1];
    #pragma unroll
    for (int off = 16; off > 0; off >>= 1)
        acc |= __shfl_xor_sync(FULLM, acc, off);
    if ((threadIdx.x & 31) == 0 && acc) atomicOr(&g_odd_or, acc);
}

// decode edges (+ self loops), clamp, histogram of dst
__global__ void prep_edges_kernel(const void* __restrict__ eiv) {
    int e = blockIdx.x * blockDim.x + threadIdx.x;
    if (e >= ET) return;
    int s, d;
    if (e < EE) {
        if (g_odd_or != 0u) {                  // int32 layout
            const int* p = (const int*)eiv;
            s = p[e];
            d = p[(size_t)EE + e];
        } else {                               // int64 layout
            const long long* p = (const long long*)eiv;
            s = (int)p[e];
            d = (int)p[(size_t)EE + e];
        }
        s = s < 0 ? 0 : (s >= NN ? NN - 1 : s);
        d = d < 0 ? 0 : (d >= NN ? NN - 1 : d);
    } else {
        s = d = e - EE;
    }
    g_src[e] = s;
    g_dst[e] = d;
    atomicAdd(&g_deg[d], 1);
}

// ---------------- exclusive scan of g_deg -> g_row ----------------
__global__ void scan_a_kernel() {
    __shared__ int part[256];
    int b = blockIdx.x, t = threadIdx.x;
    int base = b * SCAN_BLK + t * 4;
    int v[4];
    #pragma unroll
    for (int j = 0; j < 4; j++) v[j] = (base + j < NN) ? g_deg[base + j] : 0;
    int tsum = v[0] + v[1] + v[2] + v[3];
    part[t] = tsum;
    __syncthreads();
    for (int off = 1; off < 256; off <<= 1) {
        int x = (t >= off) ? part[t - off] : 0;
        __syncthreads();
        part[t] += x;
        __syncthreads();
    }
    if (t == 255) g_bsum[b] = part[255];
    int run = part[t] - tsum;
    #pragma unroll
    for (int j = 0; j < 4; j++) {
        if (base + j < NN) g_row[base + j] = run;
        run += v[j];
    }
}

// scan_b + ve fold (independent work packed into one launch)
__global__ void scan_b_kernel(const float* __restrict__ We1, const float* __restrict__ ae1v,
                              const float* __restrict__ We2, const float* __restrict__ ae2v) {
    __shared__ int sb[128];
    int t = threadIdx.x;
    int v = (t < NBLK) ? g_bsum[t] : 0;
    sb[t] = v;
    __syncthreads();
    for (int off = 1; off < 128; off <<= 1) {
        int x = (t >= off) ? sb[t - off] : 0;
        __syncthreads();
        sb[t] += x;
        __syncthreads();
    }
    if (t < NBLK) g_bscan[t] = sb[t] - v;
    // ve[h*8+d] = sum_c We[d, h*C+c] * a_edge[h, c], both layers
    if (t < 32) {
        int h = t / EDIM, d = t % EDIM;
        float s = 0.f;
        #pragma unroll
        for (int c = 0; c < 32; c++) s += We1[d * 128 + h * 32 + c] * ae1v[h * 32 + c];
        g_ve1[t] = s;
    } else if (t < 64) {
        int u = t - 32;
        int h = u / EDIM, d = u % EDIM;
        float s = 0.f;
        #pragma unroll
        for (int c = 0; c < 16; c++) s += We2[d * 64 + h * 16 + c] * ae2v[h * 16 + c];
        g_ve2[u] = s;
    }
}

__global__ void scan_c_kernel() {
    int i = blockIdx.x * blockDim.x + threadIdx.x;
    if (i < NN) {
        int r = g_row[i] + g_bscan[i / SCAN_BLK];
        g_row[i] = r;
        g_woff[i] = r;
    }
    if (i == 0) g_row[NN] = ET;
}

// scatter edges to CSR slots; fold edge-attr attention dots for BOTH layers
__global__ void scatter_kernel(const float* __restrict__ edge_attr) {
    __shared__ float v1[HH * EDIM], v2[HH * EDIM];
    if (threadIdx.x < HH * EDIM) v1[threadIdx.x] = g_ve1[threadIdx.x];
    else if (threadIdx.x < 2 * HH * EDIM) v2[threadIdx.x - HH * EDIM] = g_ve2[threadIdx.x - HH * EDIM];
    __syncthreads();
    int e = blockIdx.x * blockDim.x + threadIdx.x;
    if (e >= ET) return;
    int d = g_dst[e];
    int p = atomicAdd(&g_woff[d], 1);
    g_csrc[p] = g_src[e];
    float4 a1 = make_float4(0.f, 0.f, 0.f, 0.f);
    float4 a2 = make_float4(0.f, 0.f, 0.f, 0.f);
    if (e < EE) {
        float4 ea0 = __ldg((const float4*)(edge_attr + (size_t)e * EDIM));
        float4 ea1 = __ldg((const float4*)(edge_attr + (size_t)e * EDIM + 4));
        float eav[8] = {ea0.x, ea0.y, ea0.z, ea0.w, ea1.x, ea1.y, ea1.z, ea1.w};
        float r1[HH], r2[HH];
        #pragma unroll
        for (int h = 0; h < HH; h++) {
            float s1 = 0.f, s2 = 0.f;
            #pragma unroll
            for (int k = 0; k < EDIM; k++) {
                s1 += eav[k] * v1[h * EDIM + k];
                s2 += eav[k] * v2[h * EDIM + k];
            }
            r1[h] = s1; r2[h] = s2;
        }
        a1 = make_float4(r1[0], r1[1], r1[2], r1[3]);
        a2 = make_float4(r2[0], r2[1], r2[2], r2[3]);
    }
    ((float4*)g_ae1)[p] = a1;
    ((float4*)g_ae2)[p] = a2;
}

__device__ __forceinline__ uint2 pack_half4(float4 a) {
    __half2 h01 = __float22half2_rn(make_float2(a.x, a.y));
    __half2 h23 = __float22half2_rn(make_float2(a.z, a.w));
    uint2 u;
    u.x = *reinterpret_cast<unsigned*>(&h01);
    u.y = *reinterpret_cast<unsigned*>(&h23);
    return u;
}

// ---------------- register-tiled GEMMs (4x4 per thread) + attention dots ----------------
// layer 1: Fin=64, HC=128, C=32. 256 threads, 32 rows/block. fp16 h store, fp32 att dots.
__global__ void gemm1_kernel(const float* __restrict__ x,
                             const float* __restrict__ W,
                             const float* __restrict__ a_src,
                             const float* __restrict__ a_dst) {
    __shared__ float Ws[64 * 128];
    __shared__ float xsT[64 * 36];     // transposed, pad 36 (16B-aligned rows)
    __shared__ float asv[128], adv[128];
    int t = threadIdx.x;
    for (int i = t; i < 64 * 128; i += 256) Ws[i] = W[i];
    if (t < 128) { asv[t] = a_src[t]; adv[t] = a_dst[t]; }
    int n0 = blockIdx.x * 32;
    for (int i = t; i < 2048; i += 256) {
        int r = i >> 6, f = i & 63;
        xsT[f * 36 + r] = x[(size_t)(n0 + r) * 64 + f];
    }
    __syncthreads();

    int tx = t & 31, ty = t >> 5;
    int c0 = tx * 4;
    float4 acc0 = {0,0,0,0}, acc1 = {0,0,0,0}, acc2 = {0,0,0,0}, acc3 = {0,0,0,0};
    #pragma unroll
    for (int f = 0; f < 64; f++) {
        float4 wv = *(const float4*)&Ws[f * 128 + c0];
        float4 xv = *(const float4*)&xsT[f * 36 + ty * 4];
        acc0.x += xv.x * wv.x; acc0.y += xv.x * wv.y; acc0.z += xv.x * wv.z; acc0.w += xv.x * wv.w;
        acc1.x += xv.y * wv.x; acc1.y += xv.y * wv.y; acc1.z += xv.y * wv.z; acc1.w += xv.y * wv.w;
        acc2.x += xv.z * wv.x; acc2.y += xv.z * wv.y; acc2.z += xv.z * wv.z; acc2.w += xv.z * wv.w;
        acc3.x += xv.w * wv.x; acc3.y += xv.w * wv.y; acc3.z += xv.w * wv.z; acc3.w += xv.w * wv.w;
    }
    int head = tx >> 3;
    float4 av = *(const float4*)&asv[c0];
    float4 dv = *(const float4*)&adv[c0];
    #pragma unroll
    for (int j = 0; j < 4; j++) {
        float4 a = (j == 0) ? acc0 : (j == 1) ? acc1 : (j == 2) ? acc2 : acc3;
        int n = n0 + ty * 4 + j;
        ((uint2*)g_h16)[(size_t)n * 32 + tx] = pack_half4(a);
        float ps = a.x * av.x + a.y * av.y + a.z * av.z + a.w * av.w;
        float pd = a.x * dv.x + a.y * dv.y + a.z * dv.z + a.w * dv.w;
        #pragma unroll
        for (int off = 1; off <= 4; off <<= 1) {
            ps += __shfl_xor_sync(FULLM, ps, off);
            pd += __shfl_xor_sync(FULLM, pd, off);
        }
        if ((tx & 7) == 0) {
            g_as[n * HH + head] = ps;
            g_ad[n * HH + head] = pd;
        }
    }
}

// layer 2: Fin=32, HC=64, C=16. 128 threads, 32 rows/block.
__global__ void gemm2_kernel(const float* __restrict__ x,
                             const float* __restrict__ W,
                             const float* __restrict__ a_src,
                             const float* __restrict__ a_dst) {
    __shared__ float Ws[32 * 64];
    __shared__ float xsT[32 * 36];
    __shared__ float asv[64], adv[64];
    int t = threadIdx.x;
    for (int i = t; i < 32 * 64; i += 128) Ws[i] = W[i];
    if (t < 64) { asv[t] = a_src[t]; adv[t] = a_dst[t]; }
    int n0 = blockIdx.x * 32;
    for (int i = t; i < 1024; i += 128) {
        int r = i >> 5, f = i & 31;
        xsT[f * 36 + r] = x[(size_t)(n0 + r) * 32 + f];
    }
    __syncthreads();

    int tx = t & 15, ty = t >> 4;
    int c0 = tx * 4;
    float4 acc0 = {0,0,0,0}, acc1 = {0,0,0,0}, acc2 = {0,0,0,0}, acc3 = {0,0,0,0};
    #pragma unroll
    for (int f = 0; f < 32; f++) {
        float4 wv = *(const float4*)&Ws[f * 64 + c0];
        float4 xv = *(const float4*)&xsT[f * 36 + ty * 4];
        acc0.x += xv.x * wv.x; acc0.y += xv.x * wv.y; acc0.z += xv.x * wv.z; acc0.w += xv.x * wv.w;
        acc1.x += xv.y * wv.x; acc1.y += xv.y * wv.y; acc1.z += xv.y * wv.z; acc1.w += xv.y * wv.w;
        acc2.x += xv.z * wv.x; acc2.y += xv.z * wv.y; acc2.z += xv.z * wv.z; acc2.w += xv.z * wv.w;
        acc3.x += xv.w * wv.x; acc3.y += xv.w * wv.y; acc3.z += xv.w * wv.z; acc3.w += xv.w * wv.w;
    }
    int head = tx >> 2;
    float4 av = *(const float4*)&asv[c0];
    float4 dv = *(const float4*)&adv[c0];
    #pragma unroll
    for (int j = 0; j < 4; j++) {
        float4 a = (j == 0) ? acc0 : (j == 1) ? acc1 : (j == 2) ? acc2 : acc3;
        int n = n0 + ty * 4 + j;
        ((uint2*)g_h16)[(size_t)n * 16 + tx] = pack_half4(a);
        float ps = a.x * av.x + a.y * av.y + a.z * av.z + a.w * av.w;
        float pd = a.x * dv.x + a.y * dv.y + a.z * dv.z + a.w * dv.w;
        #pragma unroll
        for (int off = 1; off <= 2; off <<= 1) {
            ps += __shfl_xor_sync(FULLM, ps, off);
            pd += __shfl_xor_sync(FULLM, pd, off);
        }
        if ((tx & 3) == 0) {
            g_as[n * HH + head] = ps;
            g_ad[n * HH + head] = pd;
        }
    }
}

__device__ __forceinline__ float selh(float4 v, int h) {
    return h == 0 ? v.x : (h == 1 ? v.y : (h == 2 ? v.z : v.w));
}

__device__ __forceinline__ void fma_half4(float4& acc, float w, uint2 u) {
    float2 f0 = __half22float2(*reinterpret_cast<__half2*>(&u.x));
    float2 f1 = __half22float2(*reinterpret_cast<__half2*>(&u.y));
    acc.x += w * f0.x; acc.y += w * f0.y;
    acc.z += w * f1.x; acc.w += w * f1.y;
}

// single-pass fused layer (HC=128): whole warp per edge, uint2 gathers,
// 4-edge unrolled main loop (4 independent LDGs in flight), clean 1-edge tail.
__global__ void fused_layer128_kernel(const float* __restrict__ b,
                                      float* __restrict__ out,
                                      const float* __restrict__ ae_csr) {
    int n = (blockIdx.x * blockDim.x + threadIdx.x) >> 5;
    int lane = threadIdx.x & 31;
    if (n >= NN) return;
    int rs = g_row[n], re = g_row[n + 1];
    float4 ad4 = *(const float4*)&g_ad[n * HH];
    const float4* aecsr4 = (const float4*)ae_csr;
    const uint2* h2 = (const uint2*)g_h16;
    int head = lane >> 3;

    float4 acc = make_float4(0.f, 0.f, 0.f, 0.f);
    float4 ds  = make_float4(0.f, 0.f, 0.f, 0.f);

    for (int i0 = rs; i0 < re; i0 += 32) {
        int i = i0 + lane;
        int s = 0;
        float e0 = 0.f, e1 = 0.f, e2 = 0.f, e3 = 0.f;
        if (i < re) {
            s = g_csrc[i];
            float4 as4 = *(const float4*)&g_as[s * HH];
            float4 ae4 = aecsr4[i];
            float a0 = as4.x + ad4.x + ae4.x; a0 = a0 > 0.f ? a0 : NEG * a0;
            float a1 = as4.y + ad4.y + ae4.y; a1 = a1 > 0.f ? a1 : NEG * a1;
            float a2 = as4.z + ad4.z + ae4.z; a2 = a2 > 0.f ? a2 : NEG * a2;
            float a3 = as4.w + ad4.w + ae4.w; a3 = a3 > 0.f ? a3 : NEG * a3;
            e0 = __expf(a0); e1 = __expf(a1); e2 = __expf(a2); e3 = __expf(a3);
        }
        ds.x += e0; ds.y += e1; ds.z += e2; ds.w += e3;
        int cnt = min(32, re - i0);
        int j = 0;
        for (; j + 3 < cnt; j += 4) {
            int sA = __shfl_sync(FULLM, s, j);
            int sB = __shfl_sync(FULLM, s, j + 1);
            int sC = __shfl_sync(FULLM, s, j + 2);
            int sD = __shfl_sync(FULLM, s, j + 3);
            float wA0 = __shfl_sync(FULLM, e0, j), wA1 = __shfl_sync(FULLM, e1, j);
            float wA2 = __shfl_sync(FULLM, e2, j), wA3 = __shfl_sync(FULLM, e3, j);
            float wB0 = __shfl_sync(FULLM, e0, j + 1), wB1 = __shfl_sync(FULLM, e1, j + 1);
            float wB2 = __shfl_sync(FULLM, e2, j + 1), wB3 = __shfl_sync(FULLM, e3, j + 1);
            float wC0 = __shfl_sync(FULLM, e0, j + 2), wC1 = __shfl_sync(FULLM, e1, j + 2);
            float wC2 = __shfl_sync(FULLM, e2, j + 2), wC3 = __shfl_sync(FULLM, e3, j + 2);
            float wD0 = __shfl_sync(FULLM, e0, j + 3), wD1 = __shfl_sync(FULLM, e1, j + 3);
            float wD2 = __shfl_sync(FULLM, e2, j + 3), wD3 = __shfl_sync(FULLM, e3, j + 3);
            float wA = head == 0 ? wA0 : head == 1 ? wA1 : head == 2 ? wA2 : wA3;
            float wB = head == 0 ? wB0 : head == 1 ? wB1 : head == 2 ? wB2 : wB3;
            float wC = head == 0 ? wC0 : head == 1 ? wC1 : head == 2 ? wC2 : wC3;
            float wD = head == 0 ? wD0 : head == 1 ? wD1 : head == 2 ? wD2 : wD3;
            uint2 hA = h2[(size_t)sA * 32 + lane];
            uint2 hB = h2[(size_t)sB * 32 + lane];
            uint2 hC = h2[(size_t)sC * 32 + lane];
            uint2 hD = h2[(size_t)sD * 32 + lane];
            fma_half4(acc, wA, hA);
            fma_half4(acc, wB, hB);
            fma_half4(acc, wC, hC);
            fma_half4(acc, wD, hD);
        }
        for (; j < cnt; j++) {
            int sA = __shfl_sync(FULLM, s, j);
            float wA0 = __shfl_sync(FULLM, e0, j), wA1 = __shfl_sync(FULLM, e1, j);
            float wA2 = __shfl_sync(FULLM, e2, j), wA3 = __shfl_sync(FULLM, e3, j);
            float wA = head == 0 ? wA0 : head == 1 ? wA1 : head == 2 ? wA2 : wA3;
            uint2 hA = h2[(size_t)sA * 32 + lane];
            fma_half4(acc, wA, hA);
        }
    }
    #pragma unroll
    for (int off = 16; off > 0; off >>= 1) {
        ds.x += __shfl_xor_sync(FULLM, ds.x, off);
        ds.y += __shfl_xor_sync(FULLM, ds.y, off);
        ds.z += __shfl_xor_sync(FULLM, ds.z, off);
        ds.w += __shfl_xor_sync(FULLM, ds.w, off);
    }
    float rdh = 1.f / (selh(ds, head) + EPSV);
    acc.x *= rdh; acc.y *= rdh; acc.z *= rdh; acc.w *= rdh;
    // head mean: sum lanes {l, l+8, l+16, l+24}
    #pragma unroll
    for (int off = 8; off <= 16; off <<= 1) {
        acc.x += __shfl_xor_sync(FULLM, acc.x, off);
        acc.y += __shfl_xor_sync(FULLM, acc.y, off);
        acc.z += __shfl_xor_sync(FULLM, acc.z, off);
        acc.w += __shfl_xor_sync(FULLM, acc.w, off);
    }
    if (lane < 8) {
        float4 b4 = ((const float4*)b)[lane];
        float4 v;
        v.x = 0.25f * acc.x + b4.x; v.x = v.x > 0.f ? v.x : expm1f(v.x);
        v.y = 0.25f * acc.y + b4.y; v.y = v.y > 0.f ? v.y : expm1f(v.y);
        v.z = 0.25f * acc.z + b4.z; v.z = v.z > 0.f ? v.z : expm1f(v.z);
        v.w = 0.25f * acc.w + b4.w; v.w = v.w > 0.f ? v.w : expm1f(v.w);
        ((float4*)out)[(size_t)n * 8 + lane] = v;
    }
}

// single-pass fused layer (HC=64): two half-warps process alternating edges (R12 structure).
__global__ void fused_layer64_kernel(const float* __restrict__ b,
                                     float* __restrict__ out,
                                     const float* __restrict__ ae_csr) {
    int n = (blockIdx.x * blockDim.x + threadIdx.x) >> 5;
    int lane = threadIdx.x & 31;
    if (n >= NN) return;
    int rs = g_row[n], re = g_row[n + 1];
    float4 ad4 = *(const float4*)&g_ad[n * HH];
    const float4* aecsr4 = (const float4*)ae_csr;
    const uint2* h2 = (const uint2*)g_h16;
    int half = lane >> 4;
    int l = lane & 15;
    int head = l >> 2;

    float4 acc = make_float4(0.f, 0.f, 0.f, 0.f);
    float4 ds  = make_float4(0.f, 0.f, 0.f, 0.f);

    for (int i0 = rs; i0 < re; i0 += 32) {
        int i = i0 + lane;
        int s = 0;
        float e0 = 0.f, e1 = 0.f, e2 = 0.f, e3 = 0.f;
        if (i < re) {
            s = g_csrc[i];
            float4 as4 = *(const float4*)&g_as[s * HH];
            float4 ae4 = aecsr4[i];
            float a0 = as4.x + ad4.x + ae4.x; a0 = a0 > 0.f ? a0 : NEG * a0;
            float a1 = as4.y + ad4.y + ae4.y; a1 = a1 > 0.f ? a1 : NEG * a1;
            float a2 = as4.z + ad4.z + ae4.z; a2 = a2 > 0.f ? a2 : NEG * a2;
            float a3 = as4.w + ad4.w + ae4.w; a3 = a3 > 0.f ? a3 : NEG * a3;
            e0 = __expf(a0); e1 = __expf(a1); e2 = __expf(a2); e3 = __expf(a3);
        }
        ds.x += e0; ds.y += e1; ds.z += e2; ds.w += e3;
        int cnt = min(32, re - i0);
        for (int j0 = 0; j0 < cnt; j0 += 2) {
            int jj = j0 + half;
            int jc = jj < cnt ? jj : cnt - 1;
            int sj = __shfl_sync(FULLM, s, jc);
            float w0 = __shfl_sync(FULLM, e0, jc), w1 = __shfl_sync(FULLM, e1, jc);
            float w2 = __shfl_sync(FULLM, e2, jc), w3 = __shfl_sync(FULLM, e3, jc);
            if (jj < cnt) {
                float w = head == 0 ? w0 : head == 1 ? w1 : head == 2 ? w2 : w3;
                uint2 hv = h2[(size_t)sj * 16 + l];
                fma_half4(acc, w, hv);
            }
        }
    }
    #pragma unroll
    for (int off = 16; off > 0; off >>= 1) {
        ds.x += __shfl_xor_sync(FULLM, ds.x, off);
        ds.y += __shfl_xor_sync(FULLM, ds.y, off);
        ds.z += __shfl_xor_sync(FULLM, ds.z, off);
        ds.w += __shfl_xor_sync(FULLM, ds.w, off);
    }
    float rdh = 1.f / (selh(ds, head) + EPSV);
    acc.x *= rdh; acc.y *= rdh; acc.z *= rdh; acc.w *= rdh;
    #pragma unroll
    for (int k = 0; k < 3; k++) {
        int off = (k == 0) ? 16 : (k == 1 ? 4 : 8);
        acc.x += __shfl_xor_sync(FULLM, acc.x, off);
        acc.y += __shfl_xor_sync(FULLM, acc.y, off);
        acc.z += __shfl_xor_sync(FULLM, acc.z, off);
        acc.w += __shfl_xor_sync(FULLM, acc.w, off);
    }
    if (lane < 4) {
        float4 b4 = ((const float4*)b)[lane];
        float4 v;
        v.x = 0.25f * acc.x + b4.x; v.x = v.x > 0.f ? v.x : expm1f(v.x);
        v.y = 0.25f * acc.y + b4.y; v.y = v.y > 0.f ? v.y : expm1f(v.y);
        v.z = 0.25f * acc.z + b4.z; v.z = v.z > 0.f ? v.z : expm1f(v.z);
        v.w = 0.25f * acc.w + b4.w; v.w = v.w > 0.f ? v.w : expm1f(v.w);
        ((float4*)out)[(size_t)n * 4 + lane] = v;
    }
}

// ---------------- launch ----------------
extern "C" void kernel_launch(void* const* d_in, const int* in_sizes, int n_in,
                              void* d_out, int out_size) {
    const float* x   = (const float*)d_in[0];
    const void*  ei  = d_in[1];
    const float* ea  = (const float*)d_in[2];
    const float* W1  = (const float*)d_in[3];
    const float* We1 = (const float*)d_in[4];
    const float* as1 = (const float*)d_in[5];
    const float* ad1 = (const float*)d_in[6];
    const float* ae1 = (const float*)d_in[7];
    const float* b1  = (const float*)d_in[8];
    const float* W2  = (const float*)d_in[9];
    const float* We2 = (const float*)d_in[10];
    const float* as2 = (const float*)d_in[11];
    const float* ad2 = (const float*)d_in[12];
    const float* ae2 = (const float*)d_in[13];
    const float* b2  = (const float*)d_in[14];
    float* out = (float*)d_out;

    float* x2p = nullptr;
    float* ae1p = nullptr;
    float* ae2p = nullptr;
    cudaGetSymbolAddress((void**)&x2p, g_x2);
    cudaGetSymbolAddress((void**)&ae1p, g_ae1);
    cudaGetSymbolAddress((void**)&ae2p, g_ae2);

    const int TB = 256;

    // graph preprocessing (once per call) — 6 launches
    detect_kernel<<<(EE + TB - 1) / TB, TB>>>((const unsigned*)ei);
    prep_edges_kernel<<<(ET + TB - 1) / TB, TB>>>(ei);
    scan_a_kernel<<<NBLK, 256>>>();
    scan_b_kernel<<<1, 128>>>(We1, ae1, We2, ae2);
    scan_c_kernel<<<(NN + TB - 1) / TB, TB>>>();
    scatter_kernel<<<(ET + TB - 1) / TB, TB>>>(ea);

    // ---- layer 1: Fin=64, HC=128, C=32 ----
    gemm1_kernel<<<NN / 32, 256>>>(x, W1, as1, ad1);
    fused_layer128_kernel<<<(NN * 32 + TB - 1) / TB, TB>>>(b1, x2p, ae1p);

    // ---- layer 2: Fin=32, HC=64, C=16 ----
    gemm2_kernel<<<NN / 32, 128>>>(x2p, W2, as2, ad2);
    fused_layer64_kernel<<<(NN * 32 + TB - 1) / TB, TB>>>(b2, out, ae2p);
}

// round 16
// speedup vs baseline: 1.3437x; 1.3092x over previous
#include <cuda_runtime.h>
#include <cuda_fp16.h>
#include <math.h>

#define NN 100000
#define EE 1600000
#define ET 1700000          // EE + NN self loops
#define EDIM 8
#define HH 4
#define NEG 0.2f
#define EPSV 1e-16f
#define SCAN_BLK 1024
#define NBLK ((NN + SCAN_BLK - 1) / SCAN_BLK)   // 98
#define FULLM 0xffffffffu

// ---------------- static device scratch ----------------
__device__ int      g_src[ET];
__device__ int      g_dst[ET];
__device__ int      g_deg[NN];
__device__ int      g_row[NN + 1];
__device__ int      g_woff[NN];
__device__ int      g_bsum[NBLK];
__device__ int      g_bscan[NBLK];
__device__ int      g_csrc[ET];                 // CSR: src per slot
__device__ __align__(16) float  g_ae1[ET * HH]; // CSR-ordered edge attention, layer 1
__device__ __align__(16) float  g_ae2[ET * HH]; // CSR-ordered edge attention, layer 2
__device__ __align__(16) __half g_h16[NN * 128];// per-node head features, fp16 payload
__device__ __align__(16) float  g_x2[NN * 32];  // layer-2 input (fp32)
__device__ __align__(16) float  g_as[NN * HH];
__device__ __align__(16) float  g_ad[NN * HH];
__device__ float    g_ve1[HH * EDIM];
__device__ float    g_ve2[HH * EDIM];
__device__ unsigned g_odd_or = 0u;   // static zero; atomicOr is idempotent across replays

// ---------------- dtype detection (sampled, int32 vs int64) + deg zero ----------------
// Samples the odd 32-bit words of the first NN edge-index elements. If the buffer
// is int64 with values < 2^31, all odd words are 0. If int32, the odd words are
// random dst indices in [0, NN); all-zero has probability ~(1e-5)^1e5 ~ 0.
__global__ void detect_kernel(const unsigned* __restrict__ w) {
    int i = blockIdx.x * blockDim.x + threadIdx.x;
    if (i < NN) g_deg[i] = 0;
    unsigned acc = 0u;
    if (i < NN) acc = w[2 * (size_t)i + 1];
    #pragma unroll
    for (int off = 16; off > 0; off >>= 1)
        acc |= __shfl_xor_sync(FULLM, acc, off);
    if ((threadIdx.x & 31) == 0 && acc) atomicOr(&g_odd_or, acc);
}

// decode edges (+ self loops), clamp, histogram of dst
__global__ void prep_edges_kernel(const void* __restrict__ eiv) {
    int e = blockIdx.x * blockDim.x + threadIdx.x;
    if (e >= ET) return;
    int s, d;
    if (e < EE) {
        if (g_odd_or != 0u) {                  // int32 layout
            const int* p = (const int*)eiv;
            s = p[e];
            d = p[(size_t)EE + e];
        } else {                               // int64 layout
            const long long* p = (const long long*)eiv;
            s = (int)p[e];
            d = (int)p[(size_t)EE + e];
        }
        s = s < 0 ? 0 : (s >= NN ? NN - 1 : s);
        d = d < 0 ? 0 : (d >= NN ? NN - 1 : d);
    } else {
        s = d = e - EE;
    }
    g_src[e] = s;
    g_dst[e] = d;
    atomicAdd(&g_deg[d], 1);
}

// ---------------- exclusive scan of g_deg -> g_row ----------------
__global__ void scan_a_kernel() {
    __shared__ int part[256];
    int b = blockIdx.x, t = threadIdx.x;
    int base = b * SCAN_BLK + t * 4;
    int v[4];
    #pragma unroll
    for (int j = 0; j < 4; j++) v[j] = (base + j < NN) ? g_deg[base + j] : 0;
    int tsum = v[0] + v[1] + v[2] + v[3];
    part[t] = tsum;
    __syncthreads();
    for (int off = 1; off < 256; off <<= 1) {
        int x = (t >= off) ? part[t - off] : 0;
        __syncthreads();
        part[t] += x;
        __syncthreads();
    }
    if (t == 255) g_bsum[b] = part[255];
    int run = part[t] - tsum;
    #pragma unroll
    for (int j = 0; j < 4; j++) {
        if (base + j < NN) g_row[base + j] = run;
        run += v[j];
    }
}

// scan_b + ve fold (independent work packed into one launch)
__global__ void scan_b_kernel(const float* __restrict__ We1, const float* __restrict__ ae1v,
                              const float* __restrict__ We2, const float* __restrict__ ae2v) {
    __shared__ int sb[128];
    int t = threadIdx.x;
    int v = (t < NBLK) ? g_bsum[t] : 0;
    sb[t] = v;
    __syncthreads();
    for (int off = 1; off < 128; off <<= 1) {
        int x = (t >= off) ? sb[t - off] : 0;
        __syncthreads();
        sb[t] += x;
        __syncthreads();
    }
    if (t < NBLK) g_bscan[t] = sb[t] - v;
    // ve[h*8+d] = sum_c We[d, h*C+c] * a_edge[h, c], both layers
    if (t < 32) {
        int h = t / EDIM, d = t % EDIM;
        float s = 0.f;
        #pragma unroll
        for (int c = 0; c < 32; c++) s += We1[d * 128 + h * 32 + c] * ae1v[h * 32 + c];
        g_ve1[t] = s;
    } else if (t < 64) {
        int u = t - 32;
        int h = u / EDIM, d = u % EDIM;
        float s = 0.f;
        #pragma unroll
        for (int c = 0; c < 16; c++) s += We2[d * 64 + h * 16 + c] * ae2v[h * 16 + c];
        g_ve2[u] = s;
    }
}

__global__ void scan_c_kernel() {
    int i = blockIdx.x * blockDim.x + threadIdx.x;
    if (i < NN) {
        int r = g_row[i] + g_bscan[i / SCAN_BLK];
        g_row[i] = r;
        g_woff[i] = r;
    }
    if (i == 0) g_row[NN] = ET;
}

// scatter edges to CSR slots; fold edge-attr attention dots for BOTH layers
__global__ void scatter_kernel(const float* __restrict__ edge_attr) {
    __shared__ float v1[HH * EDIM], v2[HH * EDIM];
    if (threadIdx.x < HH * EDIM) v1[threadIdx.x] = g_ve1[threadIdx.x];
    else if (threadIdx.x < 2 * HH * EDIM) v2[threadIdx.x - HH * EDIM] = g_ve2[threadIdx.x - HH * EDIM];
    __syncthreads();
    int e = blockIdx.x * blockDim.x + threadIdx.x;
    if (e >= ET) return;
    int d = g_dst[e];
    int p = atomicAdd(&g_woff[d], 1);
    g_csrc[p] = g_src[e];
    float4 a1 = make_float4(0.f, 0.f, 0.f, 0.f);
    float4 a2 = make_float4(0.f, 0.f, 0.f, 0.f);
    if (e < EE) {
        float4 ea0 = __ldg((const float4*)(edge_attr + (size_t)e * EDIM));
        float4 ea1 = __ldg((const float4*)(edge_attr + (size_t)e * EDIM + 4));
        float eav[8] = {ea0.x, ea0.y, ea0.z, ea0.w, ea1.x, ea1.y, ea1.z, ea1.w};
        float r1[HH], r2[HH];
        #pragma unroll
        for (int h = 0; h < HH; h++) {
            float s1 = 0.f, s2 = 0.f;
            #pragma unroll
            for (int k = 0; k < EDIM; k++) {
                s1 += eav[k] * v1[h * EDIM + k];
                s2 += eav[k] * v2[h * EDIM + k];
            }
            r1[h] = s1; r2[h] = s2;
        }
        a1 = make_float4(r1[0], r1[1], r1[2], r1[3]);
        a2 = make_float4(r2[0], r2[1], r2[2], r2[3]);
    }
    ((float4*)g_ae1)[p] = a1;
    ((float4*)g_ae2)[p] = a2;
}

__device__ __forceinline__ uint2 pack_half4(float4 a) {
    __half2 h01 = __float22half2_rn(make_float2(a.x, a.y));
    __half2 h23 = __float22half2_rn(make_float2(a.z, a.w));
    uint2 u;
    u.x = *reinterpret_cast<unsigned*>(&h01);
    u.y = *reinterpret_cast<unsigned*>(&h23);
    return u;
}

// ---------------- register-tiled GEMMs (4x4 per thread) + attention dots ----------------
// layer 1: Fin=64, HC=128, C=32. 256 threads, 32 rows/block. fp16 h store, fp32 att dots.
__global__ void gemm1_kernel(const float* __restrict__ x,
                             const float* __restrict__ W,
                             const float* __restrict__ a_src,
                             const float* __restrict__ a_dst) {
    __shared__ float Ws[64 * 128];
    __shared__ float xsT[64 * 36];     // transposed, pad 36 (16B-aligned rows)
    __shared__ float asv[128], adv[128];
    int t = threadIdx.x;
    for (int i = t; i < 64 * 128; i += 256) Ws[i] = W[i];
    if (t < 128) { asv[t] = a_src[t]; adv[t] = a_dst[t]; }
    int n0 = blockIdx.x * 32;
    for (int i = t; i < 2048; i += 256) {
        int r = i >> 6, f = i & 63;
        xsT[f * 36 + r] = x[(size_t)(n0 + r) * 64 + f];
    }
    __syncthreads();

    int tx = t & 31, ty = t >> 5;
    int c0 = tx * 4;
    float4 acc0 = {0,0,0,0}, acc1 = {0,0,0,0}, acc2 = {0,0,0,0}, acc3 = {0,0,0,0};
    #pragma unroll
    for (int f = 0; f < 64; f++) {
        float4 wv = *(const float4*)&Ws[f * 128 + c0];
        float4 xv = *(const float4*)&xsT[f * 36 + ty * 4];
        acc0.x += xv.x * wv.x; acc0.y += xv.x * wv.y; acc0.z += xv.x * wv.z; acc0.w += xv.x * wv.w;
        acc1.x += xv.y * wv.x; acc1.y += xv.y * wv.y; acc1.z += xv.y * wv.z; acc1.w += xv.y * wv.w;
        acc2.x += xv.z * wv.x; acc2.y += xv.z * wv.y; acc2.z += xv.z * wv.z; acc2.w += xv.z * wv.w;
        acc3.x += xv.w * wv.x; acc3.y += xv.w * wv.y; acc3.z += xv.w * wv.z; acc3.w += xv.w * wv.w;
    }
    int head = tx >> 3;
    float4 av = *(const float4*)&asv[c0];
    float4 dv = *(const float4*)&adv[c0];
    #pragma unroll
    for (int j = 0; j < 4; j++) {
        float4 a = (j == 0) ? acc0 : (j == 1) ? acc1 : (j == 2) ? acc2 : acc3;
        int n = n0 + ty * 4 + j;
        ((uint2*)g_h16)[(size_t)n * 32 + tx] = pack_half4(a);
        float ps = a.x * av.x + a.y * av.y + a.z * av.z + a.w * av.w;
        float pd = a.x * dv.x + a.y * dv.y + a.z * dv.z + a.w * dv.w;
        #pragma unroll
        for (int off = 1; off <= 4; off <<= 1) {
            ps += __shfl_xor_sync(FULLM, ps, off);
            pd += __shfl_xor_sync(FULLM, pd, off);
        }
        if ((tx & 7) == 0) {
            g_as[n * HH + head] = ps;
            g_ad[n * HH + head] = pd;
        }
    }
}

// layer 2: Fin=32, HC=64, C=16. 128 threads, 32 rows/block.
__global__ void gemm2_kernel(const float* __restrict__ x,
                             const float* __restrict__ W,
                             const float* __restrict__ a_src,
                             const float* __restrict__ a_dst) {
    __shared__ float Ws[32 * 64];
    __shared__ float xsT[32 * 36];
    __shared__ float asv[64], adv[64];
    int t = threadIdx.x;
    for (int i = t; i < 32 * 64; i += 128) Ws[i] = W[i];
    if (t < 64) { asv[t] = a_src[t]; adv[t] = a_dst[t]; }
    int n0 = blockIdx.x * 32;
    for (int i = t; i < 1024; i += 128) {
        int r = i >> 5, f = i & 31;
        xsT[f * 36 + r] = x[(size_t)(n0 + r) * 32 + f];
    }
    __syncthreads();

    int tx = t & 15, ty = t >> 4;
    int c0 = tx * 4;
    float4 acc0 = {0,0,0,0}, acc1 = {0,0,0,0}, acc2 = {0,0,0,0}, acc3 = {0,0,0,0};
    #pragma unroll
    for (int f = 0; f < 32; f++) {
        float4 wv = *(const float4*)&Ws[f * 64 + c0];
        float4 xv = *(const float4*)&xsT[f * 36 + ty * 4];
        acc0.x += xv.x * wv.x; acc0.y += xv.x * wv.y; acc0.z += xv.x * wv.z; acc0.w += xv.x * wv.w;
        acc1.x += xv.y * wv.x; acc1.y += xv.y * wv.y; acc1.z += xv.y * wv.z; acc1.w += xv.y * wv.w;
        acc2.x += xv.z * wv.x; acc2.y += xv.z * wv.y; acc2.z += xv.z * wv.z; acc2.w += xv.z * wv.w;
        acc3.x += xv.w * wv.x; acc3.y += xv.w * wv.y; acc3.z += xv.w * wv.z; acc3.w += xv.w * wv.w;
    }
    int head = tx >> 2;
    float4 av = *(const float4*)&asv[c0];
    float4 dv = *(const float4*)&adv[c0];
    #pragma unroll
    for (int j = 0; j < 4; j++) {
        float4 a = (j == 0) ? acc0 : (j == 1) ? acc1 : (j == 2) ? acc2 : acc3;
        int n = n0 + ty * 4 + j;
        ((uint2*)g_h16)[(size_t)n * 16 + tx] = pack_half4(a);
        float ps = a.x * av.x + a.y * av.y + a.z * av.z + a.w * av.w;
        float pd = a.x * dv.x + a.y * dv.y + a.z * dv.z + a.w * dv.w;
        #pragma unroll
        for (int off = 1; off <= 2; off <<= 1) {
            ps += __shfl_xor_sync(FULLM, ps, off);
            pd += __shfl_xor_sync(FULLM, pd, off);
        }
        if ((tx & 3) == 0) {
            g_as[n * HH + head] = ps;
            g_ad[n * HH + head] = pd;
        }
    }
}

__device__ __forceinline__ float selh(float4 v, int h) {
    return h == 0 ? v.x : (h == 1 ? v.y : (h == 2 ? v.z : v.w));
}

__device__ __forceinline__ void fma_half4(float4& acc, float w, uint2 u) {
    float2 f0 = __half22float2(*reinterpret_cast<__half2*>(&u.x));
    float2 f1 = __half22float2(*reinterpret_cast<__half2*>(&u.y));
    acc.x += w * f0.x; acc.y += w * f0.y;
    acc.z += w * f1.x; acc.w += w * f1.y;
}

// fused layer (HC=128): phase A stages (src, exp4) for 64-edge chunks in smem,
// phase B is a shfl-free gather loop (LDS broadcasts + LDG, 4-deep pipeline).
__global__ void fused_layer128_kernel(const float* __restrict__ b,
                                      float* __restrict__ out,
                                      const float* __restrict__ ae_csr) {
    __shared__ int   sm_s[8][64];
    __shared__ float sm_w[8][256];
    int wid = threadIdx.x >> 5;
    int n = (blockIdx.x * blockDim.x + threadIdx.x) >> 5;
    int lane = threadIdx.x & 31;
    if (n >= NN) return;
    int rs = g_row[n], re = g_row[n + 1];
    float4 ad4 = *(const float4*)&g_ad[n * HH];
    const float4* aecsr4 = (const float4*)ae_csr;
    const uint2* h2 = (const uint2*)g_h16;
    int head = lane >> 3;

    float4 acc = make_float4(0.f, 0.f, 0.f, 0.f);
    float4 ds  = make_float4(0.f, 0.f, 0.f, 0.f);

    for (int i0 = rs; i0 < re; i0 += 64) {
        int lim = re - i0;
        // ---- phase A: lane-per-edge exp, staged to smem ----
        {
            int i = i0 + lane;
            if (i < re) {
                int s = g_csrc[i];
                float4 as4 = *(const float4*)&g_as[s * HH];
                float4 ae4 = aecsr4[i];
                float a0 = as4.x + ad4.x + ae4.x; a0 = a0 > 0.f ? a0 : NEG * a0;
                float a1 = as4.y + ad4.y + ae4.y; a1 = a1 > 0.f ? a1 : NEG * a1;
                float a2 = as4.z + ad4.z + ae4.z; a2 = a2 > 0.f ? a2 : NEG * a2;
                float a3 = as4.w + ad4.w + ae4.w; a3 = a3 > 0.f ? a3 : NEG * a3;
                float4 e4 = make_float4(__expf(a0), __expf(a1), __expf(a2), __expf(a3));
                sm_s[wid][lane] = s;
                ((float4*)sm_w[wid])[lane] = e4;
                ds.x += e4.x; ds.y += e4.y; ds.z += e4.z; ds.w += e4.w;
            }
        }
        if (lim > 32) {
            int i = i0 + 32 + lane;
            if (i < re) {
                int s = g_csrc[i];
                float4 as4 = *(const float4*)&g_as[s * HH];
                float4 ae4 = aecsr4[i];
                float a0 = as4.x + ad4.x + ae4.x; a0 = a0 > 0.f ? a0 : NEG * a0;
                float a1 = as4.y + ad4.y + ae4.y; a1 = a1 > 0.f ? a1 : NEG * a1;
                float a2 = as4.z + ad4.z + ae4.z; a2 = a2 > 0.f ? a2 : NEG * a2;
                float a3 = as4.w + ad4.w + ae4.w; a3 = a3 > 0.f ? a3 : NEG * a3;
                float4 e4 = make_float4(__expf(a0), __expf(a1), __expf(a2), __expf(a3));
                sm_s[wid][32 + lane] = s;
                ((float4*)sm_w[wid])[32 + lane] = e4;
                ds.x += e4.x; ds.y += e4.y; ds.z += e4.z; ds.w += e4.w;
            }
        }
        __syncwarp();
        // ---- phase B: shfl-free weighted gather ----
        int cnt = min(64, lim);
        int j = 0;
        for (; j + 3 < cnt; j += 4) {
            int s0 = sm_s[wid][j],     s1 = sm_s[wid][j + 1];
            int s2 = sm_s[wid][j + 2], s3 = sm_s[wid][j + 3];
            float w0 = sm_w[wid][(j + 0) * 4 + head];
            float w1 = sm_w[wid][(j + 1) * 4 + head];
            float w2 = sm_w[wid][(j + 2) * 4 + head];
            float w3 = sm_w[wid][(j + 3) * 4 + head];
            uint2 h0 = h2[(size_t)s0 * 32 + lane];
            uint2 h1 = h2[(size_t)s1 * 32 + lane];
            uint2 h3v = h2[(size_t)s3 * 32 + lane];
            uint2 h2v = h2[(size_t)s2 * 32 + lane];
            fma_half4(acc, w0, h0);
            fma_half4(acc, w1, h1);
            fma_half4(acc, w2, h2v);
            fma_half4(acc, w3, h3v);
        }
        for (; j < cnt; j++) {
            int s0 = sm_s[wid][j];
            float w0 = sm_w[wid][j * 4 + head];
            uint2 h0 = h2[(size_t)s0 * 32 + lane];
            fma_half4(acc, w0, h0);
        }
        __syncwarp();
    }
    #pragma unroll
    for (int off = 16; off > 0; off >>= 1) {
        ds.x += __shfl_xor_sync(FULLM, ds.x, off);
        ds.y += __shfl_xor_sync(FULLM, ds.y, off);
        ds.z += __shfl_xor_sync(FULLM, ds.z, off);
        ds.w += __shfl_xor_sync(FULLM, ds.w, off);
    }
    float rdh = 1.f / (selh(ds, head) + EPSV);
    acc.x *= rdh; acc.y *= rdh; acc.z *= rdh; acc.w *= rdh;
    // head mean: sum lanes {l, l+8, l+16, l+24}
    #pragma unroll
    for (int off = 8; off <= 16; off <<= 1) {
        acc.x += __shfl_xor_sync(FULLM, acc.x, off);
        acc.y += __shfl_xor_sync(FULLM, acc.y, off);
        acc.z += __shfl_xor_sync(FULLM, acc.z, off);
        acc.w += __shfl_xor_sync(FULLM, acc.w, off);
    }
    if (lane < 8) {
        float4 b4 = ((const float4*)b)[lane];
        float4 v;
        v.x = 0.25f * acc.x + b4.x; v.x = v.x > 0.f ? v.x : expm1f(v.x);
        v.y = 0.25f * acc.y + b4.y; v.y = v.y > 0.f ? v.y : expm1f(v.y);
        v.z = 0.25f * acc.z + b4.z; v.z = v.z > 0.f ? v.z : expm1f(v.z);
        v.w = 0.25f * acc.w + b4.w; v.w = v.w > 0.f ? v.w : expm1f(v.w);
        ((float4*)out)[(size_t)n * 8 + lane] = v;
    }
}

// fused layer (HC=64): same smem staging; two half-warps process alternating edges.
__global__ void fused_layer64_kernel(const float* __restrict__ b,
                                     float* __restrict__ out,
                                     const float* __restrict__ ae_csr) {
    __shared__ int   sm_s[8][64];
    __shared__ float sm_w[8][256];
    int wid = threadIdx.x >> 5;
    int n = (blockIdx.x * blockDim.x + threadIdx.x) >> 5;
    int lane = threadIdx.x & 31;
    if (n >= NN) return;
    int rs = g_row[n], re = g_row[n + 1];
    float4 ad4 = *(const float4*)&g_ad[n * HH];
    const float4* aecsr4 = (const float4*)ae_csr;
    const uint2* h2 = (const uint2*)g_h16;
    int half = lane >> 4;
    int l = lane & 15;
    int head = l >> 2;

    float4 acc = make_float4(0.f, 0.f, 0.f, 0.f);
    float4 ds  = make_float4(0.f, 0.f, 0.f, 0.f);

    for (int i0 = rs; i0 < re; i0 += 64) {
        int lim = re - i0;
        {
            int i = i0 + lane;
            if (i < re) {
                int s = g_csrc[i];
                float4 as4 = *(const float4*)&g_as[s * HH];
                float4 ae4 = aecsr4[i];
                float a0 = as4.x + ad4.x + ae4.x; a0 = a0 > 0.f ? a0 : NEG * a0;
                float a1 = as4.y + ad4.y + ae4.y; a1 = a1 > 0.f ? a1 : NEG * a1;
                float a2 = as4.z + ad4.z + ae4.z; a2 = a2 > 0.f ? a2 : NEG * a2;
                float a3 = as4.w + ad4.w + ae4.w; a3 = a3 > 0.f ? a3 : NEG * a3;
                float4 e4 = make_float4(__expf(a0), __expf(a1), __expf(a2), __expf(a3));
                sm_s[wid][lane] = s;
                ((float4*)sm_w[wid])[lane] = e4;
                ds.x += e4.x; ds.y += e4.y; ds.z += e4.z; ds.w += e4.w;
            }
        }
        if (lim > 32) {
            int i = i0 + 32 + lane;
            if (i < re) {
                int s = g_csrc[i];
                float4 as4 = *(const float4*)&g_as[s * HH];
                float4 ae4 = aecsr4[i];
                float a0 = as4.x + ad4.x + ae4.x; a0 = a0 > 0.f ? a0 : NEG * a0;
                float a1 = as4.y + ad4.y + ae4.y; a1 = a1 > 0.f ? a1 : NEG * a1;
                float a2 = as4.z + ad4.z + ae4.z; a2 = a2 > 0.f ? a2 : NEG * a2;
                float a3 = as4.w + ad4.w + ae4.w; a3 = a3 > 0.f ? a3 : NEG * a3;
                float4 e4 = make_float4(__expf(a0), __expf(a1), __expf(a2), __expf(a3));
                sm_s[wid][32 + lane] = s;
                ((float4*)sm_w[wid])[32 + lane] = e4;
                ds.x += e4.x; ds.y += e4.y; ds.z += e4.z; ds.w += e4.w;
            }
        }
        __syncwarp();
        int cnt = min(64, lim);
        int j = 0;
        for (; j + 3 < cnt; j += 4) {           // 4 edges per iter, 2 per half-warp
            int jA = j + half;
            int jB = j + 2 + half;
            int sA = sm_s[wid][jA], sB = sm_s[wid][jB];
            float wA = sm_w[wid][jA * 4 + head];
            float wB = sm_w[wid][jB * 4 + head];
            uint2 hA = h2[(size_t)sA * 16 + l];
            uint2 hB = h2[(size_t)sB * 16 + l];
            fma_half4(acc, wA, hA);
            fma_half4(acc, wB, hB);
        }
        for (; j < cnt; j += 2) {               // tail pairs, guarded
            int jA = j + half;
            if (jA < cnt) {
                int sA = sm_s[wid][jA];
                float wA = sm_w[wid][jA * 4 + head];
                uint2 hA = h2[(size_t)sA * 16 + l];
                fma_half4(acc, wA, hA);
            }
        }
        __syncwarp();
    }
    #pragma unroll
    for (int off = 16; off > 0; off >>= 1) {
        ds.x += __shfl_xor_sync(FULLM, ds.x, off);
        ds.y += __shfl_xor_sync(FULLM, ds.y, off);
        ds.z += __shfl_xor_sync(FULLM, ds.z, off);
        ds.w += __shfl_xor_sync(FULLM, ds.w, off);
    }
    float rdh = 1.f / (selh(ds, head) + EPSV);
    acc.x *= rdh; acc.y *= rdh; acc.z *= rdh; acc.w *= rdh;
    // combine halves (xor 16), then head mean (xor 4, 8)
    #pragma unroll
    for (int k = 0; k < 3; k++) {
        int off = (k == 0) ? 16 : (k == 1 ? 4 : 8);
        acc.x += __shfl_xor_sync(FULLM, acc.x, off);
        acc.y += __shfl_xor_sync(FULLM, acc.y, off);
        acc.z += __shfl_xor_sync(FULLM, acc.z, off);
        acc.w += __shfl_xor_sync(FULLM, acc.w, off);
    }
    if (lane < 4) {
        float4 b4 = ((const float4*)b)[lane];
        float4 v;
        v.x = 0.25f * acc.x + b4.x; v.x = v.x > 0.f ? v.x : expm1f(v.x);
        v.y = 0.25f * acc.y + b4.y; v.y = v.y > 0.f ? v.y : expm1f(v.y);
        v.z = 0.25f * acc.z + b4.z; v.z = v.z > 0.f ? v.z : expm1f(v.z);
        v.w = 0.25f * acc.w + b4.w; v.w = v.w > 0.f ? v.w : expm1f(v.w);
        ((float4*)out)[(size_t)n * 4 + lane] = v;
    }
}

// ---------------- launch ----------------
extern "C" void kernel_launch(void* const* d_in, const int* in_sizes, int n_in,
                              void* d_out, int out_size) {
    const float* x   = (const float*)d_in[0];
    const void*  ei  = d_in[1];
    const float* ea  = (const float*)d_in[2];
    const float* W1  = (const float*)d_in[3];
    const float* We1 = (const float*)d_in[4];
    const float* as1 = (const float*)d_in[5];
    const float* ad1 = (const float*)d_in[6];
    const float* ae1 = (const float*)d_in[7];
    const float* b1  = (const float*)d_in[8];
    const float* W2  = (const float*)d_in[9];
    const float* We2 = (const float*)d_in[10];
    const float* as2 = (const float*)d_in[11];
    const float* ad2 = (const float*)d_in[12];
    const float* ae2 = (const float*)d_in[13];
    const float* b2  = (const float*)d_in[14];
    float* out = (float*)d_out;

    float* x2p = nullptr;
    float* ae1p = nullptr;
    float* ae2p = nullptr;
    cudaGetSymbolAddress((void**)&x2p, g_x2);
    cudaGetSymbolAddress((void**)&ae1p, g_ae1);
    cudaGetSymbolAddress((void**)&ae2p, g_ae2);

    const int TB = 256;

    // graph preprocessing (once per call) — 6 launches
    detect_kernel<<<(NN + TB - 1) / TB, TB>>>((const unsigned*)ei);
    prep_edges_kernel<<<(ET + TB - 1) / TB, TB>>>(ei);
    scan_a_kernel<<<NBLK, 256>>>();
    scan_b_kernel<<<1, 128>>>(We1, ae1, We2, ae2);
    scan_c_kernel<<<(NN + TB - 1) / TB, TB>>>();
    scatter_kernel<<<(ET + TB - 1) / TB, TB>>>(ea);

    // ---- layer 1: Fin=64, HC=128, C=32 ----
    gemm1_kernel<<<NN / 32, 256>>>(x, W1, as1, ad1);
    fused_layer128_kernel<<<(NN * 32 + TB - 1) / TB, TB>>>(b1, x2p, ae1p);

    // ---- layer 2: Fin=32, HC=64, C=16 ----
    gemm2_kernel<<<NN / 32, 128>>>(x2p, W2, as2, ad2);
    fused_layer64_kernel<<<(NN * 32 + TB - 1) / TB, TB>>>(b2, out, ae2p);
}